// round 8
// baseline (speedup 1.0000x reference)
#include <cuda_runtime.h>

// SSIM loss, fused tiled kernel. f32x2-packed separable Gaussian convs,
// merged sliding-window H-pass, 2 blocks/SM.
// Input: denoised [32,3,512,512] f32, clean [32,3,512,512] f32.
// Output: scalar f32 = 1 - mean(ssim_map).

typedef unsigned long long u64;

#define TILE   32
#define HALO   5
#define SDIM   42            // TILE + 2*HALO
#define SSTR   43            // stage row stride in u64 (pairs)
#define HSTR   33            // hbuf row stride (u64 packed / floats scalar)
#define HIMG   512
#define WIMG   512
#define NPLANES 96
#define NPIX   (96LL*512*512)
#define TPB    256
#define GRIDX  (WIMG/TILE)
#define GRIDY  (HIMG/TILE)
#define NBLOCKS (GRIDX*GRIDY*NPLANES)   // 24576

// SMEM carve (u64 units):
//  [0 .. 2560)   vbuf region (pk1v 1024 | pk2v 1024 | sv 1024 floats) — aliases stage
//    [0 .. 1806)   stage pairs 42x43 (dead before vbuf writes)
//  [2560 .. 3946) hbuf pk1 42x33 u64
//  [3946 .. 5332) hbuf pk2 42x33 u64
//  [5332 .. 6025) hbuf scalar 42x33 floats
//  [6025 .. 6032) reduction scratch
#define OFF_STAGE 0
#define OFF_PK1V  0
#define OFF_PK2V  1024
#define OFF_SV    2048
#define OFF_HPK1  2560
#define OFF_HPK2  3946
#define OFF_HS    5332
#define OFF_RED   6025
#define SMEM_U64  6032       // 48,256 bytes < 48KB static limit

// Gaussian(sigma=1.5, 11 taps), normalized; symmetric.
#define W0 0.00102838f
#define W1 0.00759877f
#define W2 0.03600077f
#define W3 0.10936069f
#define W4 0.21300553f
#define W5 0.26601172f
// tap k -> distinct weight index min(k, 10-k), resolved at compile time
#define WIDX(k) ((k) < 5 ? (k) : 10 - (k))

__device__ float g_partials[NBLOCKS];

__device__ __forceinline__ u64 fma2(u64 a, u64 b, u64 c) {
    u64 d; asm("fma.rn.f32x2 %0, %1, %2, %3;" : "=l"(d) : "l"(a), "l"(b), "l"(c)); return d;
}
__device__ __forceinline__ u64 mul2(u64 a, u64 b) {
    u64 d; asm("mul.rn.f32x2 %0, %1, %2;" : "=l"(d) : "l"(a), "l"(b)); return d;
}
__device__ __forceinline__ u64 pack2(float lo, float hi) {
    u64 d; asm("mov.b64 %0, {%1, %2};" : "=l"(d) : "f"(lo), "f"(hi)); return d;
}
__device__ __forceinline__ void unpack2(u64 v, float& lo, float& hi) {
    asm("mov.b64 {%0, %1}, %2;" : "=f"(lo), "=f"(hi) : "l"(v));
}

__global__ __launch_bounds__(TPB, 2) void ssim_tile_kernel(
    const float* __restrict__ img1g, const float* __restrict__ img2g)
{
    __shared__ u64 smem[SMEM_U64];
    u64*   stage = smem + OFF_STAGE;
    u64*   hpk1  = smem + OFF_HPK1;
    u64*   hpk2  = smem + OFF_HPK2;
    float* hs    = (float*)(smem + OFF_HS);
    u64*   pk1v  = smem + OFF_PK1V;
    u64*   pk2v  = smem + OFF_PK2V;
    float* sv    = (float*)(smem + OFF_SV);
    float* redbuf= (float*)(smem + OFF_RED);

    const int tid = threadIdx.x;
    const int tx0 = blockIdx.x * TILE;
    const int ty0 = blockIdx.y * TILE;
    const float* p1 = img1g + (size_t)blockIdx.z * (HIMG * WIMG);
    const float* p2 = img2g + (size_t)blockIdx.z * (HIMG * WIMG);

    const float w[6] = {W0, W1, W2, W3, W4, W5};
    u64 wps[6];   // 6 distinct packed weights (symmetric kernel)
    #pragma unroll
    for (int k = 0; k < 6; ++k) wps[k] = pack2(w[k], w[k]);

    // ---- Stage: clipped 42x42 halo, both images interleaved as {x1,x2} pairs ----
    for (int idx = tid; idx < SDIM * SDIM; idx += TPB) {
        int r = idx / SDIM, c = idx - r * SDIM;
        int gy = ty0 + r - HALO, gx = tx0 + c - HALO;
        float a = 0.f, b = 0.f;
        if ((unsigned)gy < (unsigned)HIMG && (unsigned)gx < (unsigned)WIMG) {
            a = __ldg(p1 + gy * WIMG + gx);
            b = __ldg(p2 + gy * WIMG + gx);
            a = __saturatef(a);
            b = __saturatef(b);
        }
        stage[r * SSTR + c] = pack2(a, b);
    }
    __syncthreads();

    // ---- Horizontal pass (merged, sliding window): 168 units = 4 chunks x 42 rows.
    //      Each unit: 8 output cols; reads stage once; emits 3 streams:
    //      hpk1 = conv{x1,x2}, hpk2 = conv{x1^2,x2^2}, hs = conv{x1*x2}.
    if (tid < 4 * SDIM) {
        int chunk = tid / SDIM;          // 0..3 (chunk-major: warp lanes = consecutive rows)
        int r = tid - chunk * SDIM;
        int c0 = chunk << 3;
        const u64* src = stage + r * SSTR + c0;
        u64 v[18], q[18];
        float s[18];
        #pragma unroll
        for (int i = 0; i < 10; ++i) {
            u64 t = src[i];
            v[i] = t; q[i] = mul2(t, t);
            float a, b; unpack2(t, a, b); s[i] = a * b;
        }
        u64*   d1 = hpk1 + r * HSTR + c0;
        u64*   d2 = hpk2 + r * HSTR + c0;
        float* d3 = hs   + r * HSTR + c0;
        #pragma unroll
        for (int c = 0; c < 8; ++c) {
            {   // slide in one new value
                u64 t = src[10 + c];
                v[10 + c] = t; q[10 + c] = mul2(t, t);
                float a, b; unpack2(t, a, b); s[10 + c] = a * b;
            }
            u64 a1 = mul2(wps[0], v[c]);
            u64 a2 = mul2(wps[0], q[c]);
            float a3 = W0 * s[c];
            #pragma unroll
            for (int k = 1; k < 11; ++k) {
                a1 = fma2(wps[WIDX(k)], v[c + k], a1);
                a2 = fma2(wps[WIDX(k)], q[c + k], a2);
                a3 = fmaf(w[WIDX(k)], s[c + k], a3);   // const-indexed -> FFMA-imm
            }
            d1[c] = a1;
            d2[c] = a2;
            d3[c] = a3;
        }
    }
    __syncthreads();

    // ---- Vertical pass (sliding window; writes vbuf, aliasing the dead stage) ----
    {
        int ychunk = tid >> 7;       // 0 or 1 -> y0 = 0 / 16
        int u = tid & 127;
        if (u < 96) {
            int stream = u >> 5;     // 0..2
            int c = u & 31;
            int y0 = ychunk << 4;
            if (stream < 2) {
                const u64* src = (stream ? hpk2 : hpk1) + c;
                u64* dst = (stream ? pk2v : pk1v) + c;
                u64 v[26];
                #pragma unroll
                for (int i = 0; i < 10; ++i) v[i] = src[(y0 + i) * HSTR];
                #pragma unroll
                for (int y = 0; y < 16; ++y) {
                    v[10 + y] = src[(y0 + 10 + y) * HSTR];
                    u64 acc = mul2(wps[0], v[y]);
                    #pragma unroll
                    for (int k = 1; k < 11; ++k) acc = fma2(wps[WIDX(k)], v[y + k], acc);
                    dst[(y0 + y) * TILE] = acc;
                }
            } else {
                const float* src = hs + c;
                float* dst = sv + c;
                float v[26];
                #pragma unroll
                for (int i = 0; i < 10; ++i) v[i] = src[(y0 + i) * HSTR];
                #pragma unroll
                for (int y = 0; y < 16; ++y) {
                    v[10 + y] = src[(y0 + 10 + y) * HSTR];
                    float acc = W0 * v[y];
                    #pragma unroll
                    for (int k = 1; k < 11; ++k) acc = fmaf(w[WIDX(k)], v[y + k], acc);
                    dst[(y0 + y) * TILE] = acc;
                }
            }
        }
    }
    __syncthreads();

    // ---- SSIM pointwise + block reduction ----
    const float C1 = 1e-4f;   // 0.01^2
    const float C2 = 9e-4f;   // 0.03^2
    float local = 0.f;
    for (int idx = tid; idx < TILE * TILE; idx += TPB) {
        float mu1, mu2, e11, e22;
        unpack2(pk1v[idx], mu1, mu2);
        unpack2(pk2v[idx], e11, e22);
        float e12 = sv[idx];
        float mu1sq = mu1 * mu1;
        float mu2sq = mu2 * mu2;
        float mu12  = mu1 * mu2;
        float s1  = e11 - mu1sq;
        float s2  = e22 - mu2sq;
        float s12 = e12 - mu12;
        float num = (2.f * mu12 + C1) * (2.f * s12 + C2);
        float den = (mu1sq + mu2sq + C1) * (s1 + s2 + C2);
        local += __fdividef(num, den);
    }
    #pragma unroll
    for (int o = 16; o; o >>= 1) local += __shfl_down_sync(0xffffffffu, local, o);
    if ((tid & 31) == 0) redbuf[tid >> 5] = local;
    __syncthreads();
    if (tid == 0) {
        float s = 0.f;
        #pragma unroll
        for (int i = 0; i < TPB / 32; ++i) s += redbuf[i];
        int bid = (blockIdx.z * gridDim.y + blockIdx.y) * gridDim.x + blockIdx.x;
        g_partials[bid] = s;
    }
}

__global__ __launch_bounds__(1024) void ssim_reduce_kernel(float* __restrict__ out)
{
    __shared__ double sm[1024];
    const float4* p = (const float4*)g_partials;   // NBLOCKS % 4 == 0
    double s = 0.0;
    for (int i = threadIdx.x; i < NBLOCKS / 4; i += 1024) {
        float4 v = p[i];
        s += (double)v.x + (double)v.y + (double)v.z + (double)v.w;
    }
    sm[threadIdx.x] = s;
    __syncthreads();
    #pragma unroll
    for (int o = 512; o; o >>= 1) {
        if (threadIdx.x < o) sm[threadIdx.x] += sm[threadIdx.x + o];
        __syncthreads();
    }
    if (threadIdx.x == 0) out[0] = (float)(1.0 - sm[0] / (double)NPIX);
}

extern "C" void kernel_launch(void* const* d_in, const int* in_sizes, int n_in,
                              void* d_out, int out_size)
{
    const float* denoised = (const float*)d_in[0];
    const float* clean    = (const float*)d_in[1];
    dim3 grid(GRIDX, GRIDY, NPLANES);
    ssim_tile_kernel<<<grid, TPB>>>(denoised, clean);
    ssim_reduce_kernel<<<1, 1024>>>((float*)d_out);
}

// round 10
// speedup vs baseline: 1.0345x; 1.0345x over previous
#include <cuda_runtime.h>

// SSIM loss, fused tiled kernel. f32x2-packed separable Gaussian convs,
// merged sliding-window H-pass, dual-accumulator conv chains, 2 blocks/SM,
// parallel two-stage final reduce.

typedef unsigned long long u64;

#define TILE   32
#define HALO   5
#define SDIM   42            // TILE + 2*HALO
#define SSTR   43            // stage row stride in u64 (pairs)
#define HSTR   33            // hbuf row stride (u64 packed / floats scalar)
#define HIMG   512
#define WIMG   512
#define NPLANES 96
#define NPIX   (96LL*512*512)
#define TPB    256
#define GRIDX  (WIMG/TILE)
#define GRIDY  (HIMG/TILE)
#define NBLOCKS (GRIDX*GRIDY*NPLANES)   // 24576
#define RBLKS  48                        // stage-1 reduce blocks (24576/48 = 512 each)

// SMEM carve (u64 units): see prior rounds; layout unchanged.
#define OFF_STAGE 0
#define OFF_PK1V  0
#define OFF_PK2V  1024
#define OFF_SV    2048
#define OFF_HPK1  2560
#define OFF_HPK2  3946
#define OFF_HS    5332
#define OFF_RED   6025
#define SMEM_U64  6032       // 48,256 bytes < 48KB static limit

// Gaussian(sigma=1.5, 11 taps), normalized; symmetric.
#define W0 0.00102838f
#define W1 0.00759877f
#define W2 0.03600077f
#define W3 0.10936069f
#define W4 0.21300553f
#define W5 0.26601172f
#define WIDX(k) ((k) < 5 ? (k) : 10 - (k))

__device__ float g_partials[NBLOCKS];
__device__ float g_part2[RBLKS];

__device__ __forceinline__ u64 fma2(u64 a, u64 b, u64 c) {
    u64 d; asm("fma.rn.f32x2 %0, %1, %2, %3;" : "=l"(d) : "l"(a), "l"(b), "l"(c)); return d;
}
__device__ __forceinline__ u64 mul2(u64 a, u64 b) {
    u64 d; asm("mul.rn.f32x2 %0, %1, %2;" : "=l"(d) : "l"(a), "l"(b)); return d;
}
__device__ __forceinline__ u64 add2(u64 a, u64 b) {
    u64 d; asm("add.rn.f32x2 %0, %1, %2;" : "=l"(d) : "l"(a), "l"(b)); return d;
}
__device__ __forceinline__ u64 pack2(float lo, float hi) {
    u64 d; asm("mov.b64 %0, {%1, %2};" : "=l"(d) : "f"(lo), "f"(hi)); return d;
}
__device__ __forceinline__ void unpack2(u64 v, float& lo, float& hi) {
    asm("mov.b64 {%0, %1}, %2;" : "=f"(lo), "=f"(hi) : "l"(v));
}

__global__ __launch_bounds__(TPB, 2) void ssim_tile_kernel(
    const float* __restrict__ img1g, const float* __restrict__ img2g)
{
    __shared__ u64 smem[SMEM_U64];
    u64*   stage = smem + OFF_STAGE;
    u64*   hpk1  = smem + OFF_HPK1;
    u64*   hpk2  = smem + OFF_HPK2;
    float* hs    = (float*)(smem + OFF_HS);
    u64*   pk1v  = smem + OFF_PK1V;
    u64*   pk2v  = smem + OFF_PK2V;
    float* sv    = (float*)(smem + OFF_SV);
    float* redbuf= (float*)(smem + OFF_RED);

    const int tid = threadIdx.x;
    const int tx0 = blockIdx.x * TILE;
    const int ty0 = blockIdx.y * TILE;
    const float* p1 = img1g + (size_t)blockIdx.z * (HIMG * WIMG);
    const float* p2 = img2g + (size_t)blockIdx.z * (HIMG * WIMG);

    const float w[6] = {W0, W1, W2, W3, W4, W5};
    u64 wps[6];
    #pragma unroll
    for (int k = 0; k < 6; ++k) wps[k] = pack2(w[k], w[k]);

    // ---- Stage: clipped 42x42 halo, both images interleaved as {x1,x2} pairs ----
    for (int idx = tid; idx < SDIM * SDIM; idx += TPB) {
        int r = idx / SDIM, c = idx - r * SDIM;
        int gy = ty0 + r - HALO, gx = tx0 + c - HALO;
        float a = 0.f, b = 0.f;
        if ((unsigned)gy < (unsigned)HIMG && (unsigned)gx < (unsigned)WIMG) {
            a = __ldg(p1 + gy * WIMG + gx);
            b = __ldg(p2 + gy * WIMG + gx);
            a = __saturatef(a);
            b = __saturatef(b);
        }
        stage[r * SSTR + c] = pack2(a, b);
    }
    __syncthreads();

    // ---- Horizontal pass (merged, sliding window, dual accumulators) ----
    if (tid < 4 * SDIM) {
        int chunk = tid / SDIM;
        int r = tid - chunk * SDIM;
        int c0 = chunk << 3;
        const u64* src = stage + r * SSTR + c0;
        u64 v[18], q[18];
        float s[18];
        #pragma unroll
        for (int i = 0; i < 10; ++i) {
            u64 t = src[i];
            v[i] = t; q[i] = mul2(t, t);
            float a, b; unpack2(t, a, b); s[i] = a * b;
        }
        u64*   d1 = hpk1 + r * HSTR + c0;
        u64*   d2 = hpk2 + r * HSTR + c0;
        float* d3 = hs   + r * HSTR + c0;
        #pragma unroll
        for (int c = 0; c < 8; ++c) {
            {   // slide in one new value
                u64 t = src[10 + c];
                v[10 + c] = t; q[10 + c] = mul2(t, t);
                float a, b; unpack2(t, a, b); s[10 + c] = a * b;
            }
            // even/odd tap split: chain depth 6 instead of 11
            u64 a1e = mul2(wps[0], v[c]);
            u64 a1o = mul2(wps[WIDX(1)], v[c + 1]);
            u64 a2e = mul2(wps[0], q[c]);
            u64 a2o = mul2(wps[WIDX(1)], q[c + 1]);
            float a3e = W0 * s[c];
            float a3o = W1 * s[c + 1];
            #pragma unroll
            for (int k = 2; k < 11; k += 2) {
                a1e = fma2(wps[WIDX(k)], v[c + k], a1e);
                a2e = fma2(wps[WIDX(k)], q[c + k], a2e);
                a3e = fmaf(w[WIDX(k)], s[c + k], a3e);
            }
            #pragma unroll
            for (int k = 3; k < 11; k += 2) {
                a1o = fma2(wps[WIDX(k)], v[c + k], a1o);
                a2o = fma2(wps[WIDX(k)], q[c + k], a2o);
                a3o = fmaf(w[WIDX(k)], s[c + k], a3o);
            }
            d1[c] = add2(a1e, a1o);
            d2[c] = add2(a2e, a2o);
            d3[c] = a3e + a3o;
        }
    }
    __syncthreads();

    // ---- Vertical pass (sliding window, dual accumulators) ----
    {
        int ychunk = tid >> 7;
        int u = tid & 127;
        if (u < 96) {
            int stream = u >> 5;
            int c = u & 31;
            int y0 = ychunk << 4;
            if (stream < 2) {
                const u64* src = (stream ? hpk2 : hpk1) + c;
                u64* dst = (stream ? pk2v : pk1v) + c;
                u64 v[26];
                #pragma unroll
                for (int i = 0; i < 10; ++i) v[i] = src[(y0 + i) * HSTR];
                #pragma unroll
                for (int y = 0; y < 16; ++y) {
                    v[10 + y] = src[(y0 + 10 + y) * HSTR];
                    u64 ae = mul2(wps[0], v[y]);
                    u64 ao = mul2(wps[WIDX(1)], v[y + 1]);
                    #pragma unroll
                    for (int k = 2; k < 11; k += 2) ae = fma2(wps[WIDX(k)], v[y + k], ae);
                    #pragma unroll
                    for (int k = 3; k < 11; k += 2) ao = fma2(wps[WIDX(k)], v[y + k], ao);
                    dst[(y0 + y) * TILE] = add2(ae, ao);
                }
            } else {
                const float* src = hs + c;
                float* dst = sv + c;
                float v[26];
                #pragma unroll
                for (int i = 0; i < 10; ++i) v[i] = src[(y0 + i) * HSTR];
                #pragma unroll
                for (int y = 0; y < 16; ++y) {
                    v[10 + y] = src[(y0 + 10 + y) * HSTR];
                    float ae = W0 * v[y];
                    float ao = W1 * v[y + 1];
                    #pragma unroll
                    for (int k = 2; k < 11; k += 2) ae = fmaf(w[WIDX(k)], v[y + k], ae);
                    #pragma unroll
                    for (int k = 3; k < 11; k += 2) ao = fmaf(w[WIDX(k)], v[y + k], ao);
                    dst[(y0 + y) * TILE] = ae + ao;
                }
            }
        }
    }
    __syncthreads();

    // ---- SSIM pointwise + block reduction ----
    const float C1 = 1e-4f;
    const float C2 = 9e-4f;
    float local = 0.f;
    for (int idx = tid; idx < TILE * TILE; idx += TPB) {
        float mu1, mu2, e11, e22;
        unpack2(pk1v[idx], mu1, mu2);
        unpack2(pk2v[idx], e11, e22);
        float e12 = sv[idx];
        float mu1sq = mu1 * mu1;
        float mu2sq = mu2 * mu2;
        float mu12  = mu1 * mu2;
        float s1  = e11 - mu1sq;
        float s2  = e22 - mu2sq;
        float s12 = e12 - mu12;
        float num = (2.f * mu12 + C1) * (2.f * s12 + C2);
        float den = (mu1sq + mu2sq + C1) * (s1 + s2 + C2);
        local += __fdividef(num, den);
    }
    #pragma unroll
    for (int o = 16; o; o >>= 1) local += __shfl_down_sync(0xffffffffu, local, o);
    if ((tid & 31) == 0) redbuf[tid >> 5] = local;
    __syncthreads();
    if (tid == 0) {
        float s = 0.f;
        #pragma unroll
        for (int i = 0; i < TPB / 32; ++i) s += redbuf[i];
        int bid = (blockIdx.z * gridDim.y + blockIdx.y) * gridDim.x + blockIdx.x;
        g_partials[bid] = s;
    }
}

// Stage-1 reduce: 48 blocks x 256 threads, each block sums 512 partials.
__global__ __launch_bounds__(256) void ssim_reduce1_kernel()
{
    __shared__ float sm[8];
    const float4* p = (const float4*)g_partials;
    int base = blockIdx.x * 128;           // 128 float4 = 512 floats per block
    float s = 0.f;
    if (threadIdx.x < 128) {
        float4 v = p[base + threadIdx.x];
        s = v.x + v.y + v.z + v.w;
    }
    #pragma unroll
    for (int o = 16; o; o >>= 1) s += __shfl_down_sync(0xffffffffu, s, o);
    if ((threadIdx.x & 31) == 0) sm[threadIdx.x >> 5] = s;
    __syncthreads();
    if (threadIdx.x == 0) {
        float t = 0.f;
        #pragma unroll
        for (int i = 0; i < 8; ++i) t += sm[i];
        g_part2[blockIdx.x] = t;
    }
}

// Stage-2 reduce: one warp sums the 48 stage-1 partials in double.
__global__ void ssim_reduce2_kernel(float* __restrict__ out)
{
    int t = threadIdx.x;                   // 32 threads
    double s = (t < RBLKS) ? (double)g_part2[t] : 0.0;
    if (t + 32 < RBLKS) s += (double)g_part2[t + 32];
    #pragma unroll
    for (int o = 16; o; o >>= 1) s += __shfl_down_sync(0xffffffffu, s, o);
    if (t == 0) out[0] = (float)(1.0 - s / (double)NPIX);
}

extern "C" void kernel_launch(void* const* d_in, const int* in_sizes, int n_in,
                              void* d_out, int out_size)
{
    const float* denoised = (const float*)d_in[0];
    const float* clean    = (const float*)d_in[1];
    dim3 grid(GRIDX, GRIDY, NPLANES);
    ssim_tile_kernel<<<grid, TPB>>>(denoised, clean);
    ssim_reduce1_kernel<<<RBLKS, 256>>>();
    ssim_reduce2_kernel<<<1, 32>>>((float*)d_out);
}

// round 12
// speedup vs baseline: 1.2245x; 1.1837x over previous
#include <cuda_runtime.h>

// SSIM loss, fused tiled kernel. f32x2-packed separable Gaussian convs.
// Stream-split sliding-window H-pass (low reg pressure), 4 blocks/SM,
// parallel two-stage final reduce.

typedef unsigned long long u64;

#define TILE   32
#define HALO   5
#define SDIM   42            // TILE + 2*HALO
#define SSTR   43            // stage row stride in u64 (pairs)
#define HSTR   33            // hbuf row stride (u64 packed / floats scalar)
#define HIMG   512
#define WIMG   512
#define NPLANES 96
#define NPIX   (96LL*512*512)
#define TPB    256
#define GRIDX  (WIMG/TILE)
#define GRIDY  (HIMG/TILE)
#define NBLOCKS (GRIDX*GRIDY*NPLANES)   // 24576
#define RBLKS  48

// SMEM carve (u64 units):
//  [0 .. 2560)   vbuf (pk1v 1024 | pk2v 1024 | sv 1024 f32) — aliases stage
//    [0 .. 1806)   stage pairs 42x43 (dead before vbuf writes)
//  [2560 .. 3946) hbuf pk1 42x33 u64
//  [3946 .. 5332) hbuf pk2 42x33 u64
//  [5332 .. 6025) hbuf scalar 42x33 f32
//  [6025 .. 6032) reduction scratch
#define OFF_STAGE 0
#define OFF_PK1V  0
#define OFF_PK2V  1024
#define OFF_SV    2048
#define OFF_HPK1  2560
#define OFF_HPK2  3946
#define OFF_HS    5332
#define OFF_RED   6025
#define SMEM_U64  6032       // 48,256 B < 48KB static limit; 4 blocks = 193KB/SM

// Gaussian(sigma=1.5, 11 taps), normalized; symmetric.
#define W0 0.00102838f
#define W1 0.00759877f
#define W2 0.03600077f
#define W3 0.10936069f
#define W4 0.21300553f
#define W5 0.26601172f
#define WIDX(k) ((k) < 5 ? (k) : 10 - (k))

__device__ float g_partials[NBLOCKS];
__device__ float g_part2[RBLKS];

__device__ __forceinline__ u64 fma2(u64 a, u64 b, u64 c) {
    u64 d; asm("fma.rn.f32x2 %0, %1, %2, %3;" : "=l"(d) : "l"(a), "l"(b), "l"(c)); return d;
}
__device__ __forceinline__ u64 mul2(u64 a, u64 b) {
    u64 d; asm("mul.rn.f32x2 %0, %1, %2;" : "=l"(d) : "l"(a), "l"(b)); return d;
}
__device__ __forceinline__ u64 add2(u64 a, u64 b) {
    u64 d; asm("add.rn.f32x2 %0, %1, %2;" : "=l"(d) : "l"(a), "l"(b)); return d;
}
__device__ __forceinline__ u64 pack2(float lo, float hi) {
    u64 d; asm("mov.b64 %0, {%1, %2};" : "=l"(d) : "f"(lo), "f"(hi)); return d;
}
__device__ __forceinline__ void unpack2(u64 v, float& lo, float& hi) {
    asm("mov.b64 {%0, %1}, %2;" : "=f"(lo), "=f"(hi) : "l"(v));
}

__global__ __launch_bounds__(TPB, 4) void ssim_tile_kernel(
    const float* __restrict__ img1g, const float* __restrict__ img2g)
{
    __shared__ u64 smem[SMEM_U64];
    u64*   stage = smem + OFF_STAGE;
    u64*   hpk1  = smem + OFF_HPK1;
    u64*   hpk2  = smem + OFF_HPK2;
    float* hs    = (float*)(smem + OFF_HS);
    u64*   pk1v  = smem + OFF_PK1V;
    u64*   pk2v  = smem + OFF_PK2V;
    float* sv    = (float*)(smem + OFF_SV);
    float* redbuf= (float*)(smem + OFF_RED);

    const int tid = threadIdx.x;
    const int tx0 = blockIdx.x * TILE;
    const int ty0 = blockIdx.y * TILE;
    const float* p1 = img1g + (size_t)blockIdx.z * (HIMG * WIMG);
    const float* p2 = img2g + (size_t)blockIdx.z * (HIMG * WIMG);

    const float w[6] = {W0, W1, W2, W3, W4, W5};
    u64 wps[6];
    #pragma unroll
    for (int k = 0; k < 6; ++k) wps[k] = pack2(w[k], w[k]);

    // ---- Stage: clipped 42x42 halo, both images interleaved as {x1,x2} pairs ----
    for (int idx = tid; idx < SDIM * SDIM; idx += TPB) {
        int r = idx / SDIM, c = idx - r * SDIM;
        int gy = ty0 + r - HALO, gx = tx0 + c - HALO;
        float a = 0.f, b = 0.f;
        if ((unsigned)gy < (unsigned)HIMG && (unsigned)gx < (unsigned)WIMG) {
            a = __ldg(p1 + gy * WIMG + gx);
            b = __ldg(p2 + gy * WIMG + gx);
            a = __saturatef(a);
            b = __saturatef(b);
        }
        stage[r * SSTR + c] = pack2(a, b);
    }
    __syncthreads();

    // ---- Horizontal pass (stream-split, sliding window, dual accumulators) ----
    // 252 units: stream s (0:pairs, 1:squares, 2:product) x 42 rows x 2 16-col chunks.
    if (tid < 252) {
        int s = tid / 84;
        int t = tid - s * 84;
        int h = t / 42;
        int r = t - h * 42;
        int c0 = h << 4;
        const u64* src = stage + r * SSTR + c0;
        if (s == 0) {
            u64* dst = hpk1 + r * HSTR + c0;
            u64 v[26];
            #pragma unroll
            for (int i = 0; i < 10; ++i) v[i] = src[i];
            #pragma unroll
            for (int c = 0; c < 16; ++c) {
                v[10 + c] = src[10 + c];
                u64 ae = mul2(wps[0], v[c]);
                u64 ao = mul2(wps[1], v[c + 1]);
                #pragma unroll
                for (int k = 2; k < 11; k += 2) ae = fma2(wps[WIDX(k)], v[c + k], ae);
                #pragma unroll
                for (int k = 3; k < 11; k += 2) ao = fma2(wps[WIDX(k)], v[c + k], ao);
                dst[c] = add2(ae, ao);
            }
        } else if (s == 1) {
            u64* dst = hpk2 + r * HSTR + c0;
            u64 v[26];
            #pragma unroll
            for (int i = 0; i < 10; ++i) { u64 t2 = src[i]; v[i] = mul2(t2, t2); }
            #pragma unroll
            for (int c = 0; c < 16; ++c) {
                { u64 t2 = src[10 + c]; v[10 + c] = mul2(t2, t2); }
                u64 ae = mul2(wps[0], v[c]);
                u64 ao = mul2(wps[1], v[c + 1]);
                #pragma unroll
                for (int k = 2; k < 11; k += 2) ae = fma2(wps[WIDX(k)], v[c + k], ae);
                #pragma unroll
                for (int k = 3; k < 11; k += 2) ao = fma2(wps[WIDX(k)], v[c + k], ao);
                dst[c] = add2(ae, ao);
            }
        } else {
            float* dst = hs + r * HSTR + c0;
            float v[26];
            #pragma unroll
            for (int i = 0; i < 10; ++i) { float a, b; unpack2(src[i], a, b); v[i] = a * b; }
            #pragma unroll
            for (int c = 0; c < 16; ++c) {
                { float a, b; unpack2(src[10 + c], a, b); v[10 + c] = a * b; }
                float ae = W0 * v[c];
                float ao = W1 * v[c + 1];
                #pragma unroll
                for (int k = 2; k < 11; k += 2) ae = fmaf(w[WIDX(k)], v[c + k], ae);
                #pragma unroll
                for (int k = 3; k < 11; k += 2) ao = fmaf(w[WIDX(k)], v[c + k], ao);
                dst[c] = ae + ao;
            }
        }
    }
    __syncthreads();

    // ---- Vertical pass (sliding window, dual accumulators; writes vbuf over dead stage) ----
    {
        int ychunk = tid >> 7;
        int u = tid & 127;
        if (u < 96) {
            int stream = u >> 5;
            int c = u & 31;
            int y0 = ychunk << 4;
            if (stream < 2) {
                const u64* src = (stream ? hpk2 : hpk1) + c;
                u64* dst = (stream ? pk2v : pk1v) + c;
                u64 v[26];
                #pragma unroll
                for (int i = 0; i < 10; ++i) v[i] = src[(y0 + i) * HSTR];
                #pragma unroll
                for (int y = 0; y < 16; ++y) {
                    v[10 + y] = src[(y0 + 10 + y) * HSTR];
                    u64 ae = mul2(wps[0], v[y]);
                    u64 ao = mul2(wps[1], v[y + 1]);
                    #pragma unroll
                    for (int k = 2; k < 11; k += 2) ae = fma2(wps[WIDX(k)], v[y + k], ae);
                    #pragma unroll
                    for (int k = 3; k < 11; k += 2) ao = fma2(wps[WIDX(k)], v[y + k], ao);
                    dst[(y0 + y) * TILE] = add2(ae, ao);
                }
            } else {
                const float* src = hs + c;
                float* dst = sv + c;
                float v[26];
                #pragma unroll
                for (int i = 0; i < 10; ++i) v[i] = src[(y0 + i) * HSTR];
                #pragma unroll
                for (int y = 0; y < 16; ++y) {
                    v[10 + y] = src[(y0 + 10 + y) * HSTR];
                    float ae = W0 * v[y];
                    float ao = W1 * v[y + 1];
                    #pragma unroll
                    for (int k = 2; k < 11; k += 2) ae = fmaf(w[WIDX(k)], v[y + k], ae);
                    #pragma unroll
                    for (int k = 3; k < 11; k += 2) ao = fmaf(w[WIDX(k)], v[y + k], ao);
                    dst[(y0 + y) * TILE] = ae + ao;
                }
            }
        }
    }
    __syncthreads();

    // ---- SSIM pointwise + block reduction ----
    const float C1 = 1e-4f;
    const float C2 = 9e-4f;
    float local = 0.f;
    #pragma unroll
    for (int it = 0; it < 4; ++it) {
        int idx = tid + it * TPB;
        float mu1, mu2, e11, e22;
        unpack2(pk1v[idx], mu1, mu2);
        unpack2(pk2v[idx], e11, e22);
        float e12 = sv[idx];
        float mu1sq = mu1 * mu1;
        float mu2sq = mu2 * mu2;
        float mu12  = mu1 * mu2;
        float s1  = e11 - mu1sq;
        float s2  = e22 - mu2sq;
        float s12 = e12 - mu12;
        float num = (2.f * mu12 + C1) * (2.f * s12 + C2);
        float den = (mu1sq + mu2sq + C1) * (s1 + s2 + C2);
        local += __fdividef(num, den);
    }
    #pragma unroll
    for (int o = 16; o; o >>= 1) local += __shfl_down_sync(0xffffffffu, local, o);
    if ((tid & 31) == 0) redbuf[tid >> 5] = local;
    __syncthreads();
    if (tid == 0) {
        float s = 0.f;
        #pragma unroll
        for (int i = 0; i < TPB / 32; ++i) s += redbuf[i];
        int bid = (blockIdx.z * gridDim.y + blockIdx.y) * gridDim.x + blockIdx.x;
        g_partials[bid] = s;
    }
}

// Stage-1 reduce: 48 blocks x 256 threads, each block sums 512 partials.
__global__ __launch_bounds__(256) void ssim_reduce1_kernel()
{
    __shared__ float sm[8];
    const float4* p = (const float4*)g_partials;
    int base = blockIdx.x * 128;
    float s = 0.f;
    if (threadIdx.x < 128) {
        float4 v = p[base + threadIdx.x];
        s = v.x + v.y + v.z + v.w;
    }
    #pragma unroll
    for (int o = 16; o; o >>= 1) s += __shfl_down_sync(0xffffffffu, s, o);
    if ((threadIdx.x & 31) == 0) sm[threadIdx.x >> 5] = s;
    __syncthreads();
    if (threadIdx.x == 0) {
        float t = 0.f;
        #pragma unroll
        for (int i = 0; i < 8; ++i) t += sm[i];
        g_part2[blockIdx.x] = t;
    }
}

// Stage-2 reduce: one warp sums the 48 stage-1 partials in double.
__global__ void ssim_reduce2_kernel(float* __restrict__ out)
{
    int t = threadIdx.x;
    double s = (t < RBLKS) ? (double)g_part2[t] : 0.0;
    if (t + 32 < RBLKS) s += (double)g_part2[t + 32];
    #pragma unroll
    for (int o = 16; o; o >>= 1) s += __shfl_down_sync(0xffffffffu, s, o);
    if (t == 0) out[0] = (float)(1.0 - s / (double)NPIX);
}

extern "C" void kernel_launch(void* const* d_in, const int* in_sizes, int n_in,
                              void* d_out, int out_size)
{
    const float* denoised = (const float*)d_in[0];
    const float* clean    = (const float*)d_in[1];
    dim3 grid(GRIDX, GRIDY, NPLANES);
    ssim_tile_kernel<<<grid, TPB>>>(denoised, clean);
    ssim_reduce1_kernel<<<RBLKS, 256>>>();
    ssim_reduce2_kernel<<<1, 32>>>((float*)d_out);
}